// round 11
// baseline (speedup 1.0000x reference)
#include <cuda_runtime.h>

// DiffAttention: x(1,128,32,32,32) fp32, w_qkv(384,128) fp32.
// Subsample stride 2 -> xs(128, 4096 tokens). qkv = w @ xs -> (4 heads, 96, 4096).
// out[h,n,d] = sum_m (softmax1 - 0.1*softmax2)[n,m] * v[m,d], scale = 1/sqrt(32).

#define NHEADS 4
#define DHEAD  32
#define NTOK   4096
#define LAMBDA 0.1f
// (1/sqrt(32)) * log2(e): fold scale + exp->ex2 conversion into q.
#define QSCALE 0.2550565488136659f

typedef unsigned long long ull;

// Persistent scratch (no allocation allowed in kernel_launch).
__device__ float Xs[128 * NTOK];              // compact subsampled input
__device__ float Qg[NHEADS * NTOK * DHEAD];
__device__ float Kg[NHEADS * NTOK * DHEAD];
__device__ float Vg[NHEADS * NTOK * DHEAD];
// Partials: [4096 items][32 rows][68] : 32 acc1, 32 acc2, l1, l2, pad
__device__ float Pacc[4096 * 32 * 68];

__device__ __forceinline__ ull fma2(ull a, ull b, ull c) {
    ull d;
    asm("fma.rn.f32x2 %0, %1, %2, %3;" : "=l"(d) : "l"(a), "l"(b), "l"(c));
    return d;
}
__device__ __forceinline__ ull add2(ull a, ull b) {
    ull d;
    asm("add.rn.f32x2 %0, %1, %2;" : "=l"(d) : "l"(a), "l"(b));
    return d;
}
__device__ __forceinline__ ull pack2(float lo, float hi) {
    ull d;
    asm("mov.b64 %0, {%1, %2};" : "=l"(d) : "f"(lo), "f"(hi));
    return d;
}
__device__ __forceinline__ float2 unpack2(ull a) {
    float2 r;
    asm("mov.b64 {%0, %1}, %2;" : "=f"(r.x), "=f"(r.y) : "l"(a));
    return r;
}
__device__ __forceinline__ float ex2(float x) {
    float y;
    asm("ex2.approx.f32 %0, %1;" : "=f"(y) : "f"(x));
    return y;
}

// ---------------------------------------------------------------------------
// Gather the stride-2 subsample into a compact channel-major buffer.
// Xs[c][n], n = hh*256 + ww*16 + zz. grid 512 x 256, 4 elems/thread.
// ---------------------------------------------------------------------------
__global__ void __launch_bounds__(256) gather_kernel(const float* __restrict__ x) {
    int idx = blockIdx.x * 1024 + threadIdx.x;
#pragma unroll
    for (int i = 0; i < 4; i++, idx += 256) {
        const int c = idx >> 12;
        const int n = idx & 4095;
        const int hh = n >> 8, ww = (n >> 4) & 15, zz = n & 15;
        Xs[idx] = x[c * 32768 + hh * 2048 + ww * 64 + zz * 2];
    }
}

// ---------------------------------------------------------------------------
// QKV projection from compact Xs: block = 16 output channels x 256 tokens.
// grid (16 token-tiles, 24 o-groups), 256 threads. f32x2 inner loop.
// ---------------------------------------------------------------------------
__global__ void __launch_bounds__(256) qkv_kernel(const float* __restrict__ w) {
    __shared__ float wsT[128 * 18];   // [c][16 outputs + 2 pad], pair-aligned
    const int og  = blockIdx.y;       // 0..23 -> channels og*16 .. og*16+15
    const int nt  = blockIdx.x;       // 0..15
    const int tid = threadIdx.x;

    for (int i = tid; i < 16 * 128; i += 256) {
        const int j = i >> 7, c = i & 127;
        wsT[c * 18 + j] = w[(og * 16 + j) * 128 + c];
    }
    __syncthreads();

    const int n = nt * 256 + tid;     // token index

    ull acc[8];
#pragma unroll
    for (int j = 0; j < 8; j++) acc[j] = 0ull;

#pragma unroll 4
    for (int c = 0; c < 128; c++) {
        const float xv = Xs[c * 4096 + n];
        const ull xp = pack2(xv, xv);
        const ull* wp = (const ull*)(wsT + c * 18);
#pragma unroll
        for (int j = 0; j < 8; j++) acc[j] = fma2(xp, wp[j], acc[j]);
    }

#pragma unroll
    for (int j = 0; j < 8; j++) {
        const float2 a = unpack2(acc[j]);
        const int o0 = og * 16 + 2 * j;
        {
            const int head = o0 / 96, r = o0 % 96;
            float* dst = (r < 32) ? Qg : (r < 64 ? Kg : Vg);
            const int d = (r < 32) ? r : (r < 64 ? r - 32 : r - 64);
            dst[(head * NTOK + n) * DHEAD + d] = a.x;
        }
        {
            const int o1 = o0 + 1;
            const int head = o1 / 96, r = o1 % 96;
            float* dst = (r < 32) ? Qg : (r < 64 ? Kg : Vg);
            const int d = (r < 32) ? r : (r < 64 ? r - 32 : r - 64);
            dst[(head * NTOK + n) * DHEAD + d] = a.y;
        }
    }
}

// ---------------------------------------------------------------------------
// Differential flash attention partial pass.
// grid 4096 = 4 heads * 128 row-tiles * 8 key-eighths (512 keys each).
// Block: 128 threads = 4 warps, lane = query row; warp w takes m%4==w.
// No-max online softmax (scores O(1), exp can't overflow).
// ---------------------------------------------------------------------------
__global__ void __launch_bounds__(128, 4) attn_kernel() {
    __shared__ __align__(16) float sbuf[8448];   // tiles 8192; reduce 8448
    float* ks = sbuf;            // [128][32]
    float* vs = sbuf + 4096;     // [128][32]

    const int tid  = threadIdx.x;
    const int lane = tid & 31;
    const int warp = tid >> 5;
    const int bid  = blockIdx.x;
    const int kq   = bid & 7;                // key eighth
    const int tile = (bid >> 3) & 127;
    const int h    = bid >> 10;
    const int row  = tile * 32 + lane;

    // Load q row (32 floats), pre-scaled by scale*log2e, as 16 packed f32x2.
    const float2* qv = (const float2*)(Qg + (h * NTOK + row) * DHEAD);
    ull q1p[8], q2p[8];
#pragma unroll
    for (int j = 0; j < 8; j++) {
        const float2 a = qv[j];
        const float2 b = qv[8 + j];
        q1p[j] = pack2(a.x * QSCALE, a.y * QSCALE);
        q2p[j] = pack2(b.x * QSCALE, b.y * QSCALE);
    }

    ull acc1[16], acc2[16];
#pragma unroll
    for (int j = 0; j < 16; j++) { acc1[j] = 0ull; acc2[j] = 0ull; }
    float l1 = 0.f, l2 = 0.f;

    const float* Kh = Kg + h * NTOK * DHEAD;
    const float* Vh = Vg + h * NTOK * DHEAD;

    for (int mt = 0; mt < 4; mt++) {
        __syncthreads();
        // Stage this tile's K/V (128 keys x 32 floats) -> shared, coalesced.
        const int base4 = (kq * 512 + mt * 128) * 8;   // float4 index
#pragma unroll
        for (int i = 0; i < 8; i++) {
            const int idx = tid + i * 128;
            ((float4*)ks)[idx] = ((const float4*)Kh)[base4 + idx];
            ((float4*)vs)[idx] = ((const float4*)Vh)[base4 + idx];
        }
        __syncthreads();

#pragma unroll 2
        for (int mi = 0; mi < 32; mi++) {
            const int mm = mi * 4 + warp;
            const longlong2* kr = (const longlong2*)(ks + mm * 32);

            ull s1a = 0ull, s1b = 0ull, s2a = 0ull, s2b = 0ull;
#pragma unroll
            for (int j = 0; j < 4; j++) {
                const longlong2 ka = kr[j];       // k1 dims 4j..4j+3
                const longlong2 kb = kr[4 + j];   // k2 dims 4j..4j+3
                s1a = fma2(q1p[2 * j],     (ull)ka.x, s1a);
                s1b = fma2(q1p[2 * j + 1], (ull)ka.y, s1b);
                s2a = fma2(q2p[2 * j],     (ull)kb.x, s2a);
                s2b = fma2(q2p[2 * j + 1], (ull)kb.y, s2b);
            }
            const float2 f1 = unpack2(add2(s1a, s1b));
            const float2 f2 = unpack2(add2(s2a, s2b));
            const float e1 = ex2(f1.x + f1.y);
            const float e2 = ex2(f2.x + f2.y);
            l1 += e1; l2 += e2;
            const ull e1p = pack2(e1, e1);
            const ull e2p = pack2(e2, e2);

            const longlong2* vr = (const longlong2*)(vs + mm * 32);
#pragma unroll
            for (int j = 0; j < 8; j++) {
                const longlong2 vv = vr[j];
                acc1[2 * j]     = fma2(e1p, (ull)vv.x, acc1[2 * j]);
                acc1[2 * j + 1] = fma2(e1p, (ull)vv.y, acc1[2 * j + 1]);
                acc2[2 * j]     = fma2(e2p, (ull)vv.x, acc2[2 * j]);
                acc2[2 * j + 1] = fma2(e2p, (ull)vv.y, acc2[2 * j + 1]);
            }
        }
    }

    // --- merge the 4 warp partials through shared memory ---
    __syncthreads();
    float* red = sbuf;                            // [4][32][66]
    float* my  = red + (warp * 32 + lane) * 66;
#pragma unroll
    for (int j = 0; j < 16; j++) {
        const float2 a = unpack2(acc1[j]);
        const float2 b = unpack2(acc2[j]);
        my[2 * j]          = a.x;  my[2 * j + 1]      = a.y;
        my[32 + 2 * j]     = b.x;  my[32 + 2 * j + 1] = b.y;
    }
    my[64] = l1;  my[65] = l2;
    __syncthreads();

    const int r  = tid >> 2;          // row 0..31
    const int dg = (tid & 3) * 8;     // 8-wide d chunk
    float* P = Pacc + ((size_t)bid * 32 + r) * 68;

#pragma unroll
    for (int d = 0; d < 8; d++) {
        float a = 0.f, b = 0.f;
#pragma unroll
        for (int w = 0; w < 4; w++) {
            a += red[(w * 32 + r) * 66 + dg + d];
            b += red[(w * 32 + r) * 66 + 32 + dg + d];
        }
        P[dg + d]      = a;
        P[32 + dg + d] = b;
    }
    if ((tid & 3) == 0) {
        float l1t = 0.f, l2t = 0.f;
#pragma unroll
        for (int w = 0; w < 4; w++) {
            l1t += red[(w * 32 + r) * 66 + 64];
            l2t += red[(w * 32 + r) * 66 + 65];
        }
        P[64] = l1t;  P[65] = l2t;
    }
}

// ---------------------------------------------------------------------------
// Merge the 8 key-eighth partials and normalize. grid 512, 128 threads.
// ---------------------------------------------------------------------------
__global__ void __launch_bounds__(128) merge_kernel(float* __restrict__ out) {
    const int tid  = threadIdx.x;
    const int r    = tid >> 2;
    const int dg   = (tid & 3) * 8;
    const int h    = blockIdx.x >> 7;
    const int tile = blockIdx.x & 127;

    const float* P0 = Pacc + (((size_t)blockIdx.x * 8) * 32 + r) * 68;

    float l1 = 0.f, l2 = 0.f;
#pragma unroll
    for (int q = 0; q < 8; q++) {
        l1 += P0[q * 32 * 68 + 64];
        l2 += P0[q * 32 * 68 + 65];
    }
    const float inv1 = 1.f / l1;
    const float inv2 = LAMBDA / l2;

    float* op = out + h * (NTOK * DHEAD) + (tile * 32 + r) * DHEAD + dg;
#pragma unroll
    for (int d = 0; d < 8; d++) {
        float a = 0.f, b = 0.f;
#pragma unroll
        for (int q = 0; q < 8; q++) {
            a += P0[q * 32 * 68 + dg + d];
            b += P0[q * 32 * 68 + 32 + dg + d];
        }
        op[d] = a * inv1 - b * inv2;
    }
}

// ---------------------------------------------------------------------------
extern "C" void kernel_launch(void* const* d_in, const int* in_sizes, int n_in,
                              void* d_out, int out_size) {
    const float* x = (const float*)d_in[0];   // (1,128,32,32,32)
    const float* w = (const float*)d_in[1];   // (384,128)
    float* out = (float*)d_out;               // (1,128,16,16,16) fp32

    gather_kernel<<<512, 256>>>(x);
    dim3 qgrid(16, 24);
    qkv_kernel<<<qgrid, 256>>>(w);
    attn_kernel<<<NHEADS * 128 * 8, 128>>>();
    merge_kernel<<<NHEADS * 128, 128>>>(out);
}

// round 15
// speedup vs baseline: 1.0050x; 1.0050x over previous
#include <cuda_runtime.h>

// DiffAttention: x(1,128,32,32,32) fp32, w_qkv(384,128) fp32.
// Subsample stride 2 -> xs(128, 4096 tokens). qkv = w @ xs -> (4 heads, 96, 4096).
// out[h,n,d] = sum_m (softmax1 - 0.1*softmax2)[n,m] * v[m,d], scale = 1/sqrt(32).

#define NHEADS 4
#define DHEAD  32
#define NTOK   4096
#define LAMBDA 0.1f
// (1/sqrt(32)) * log2(e): fold scale + exp->ex2 conversion into q.
#define QSCALE 0.2550565488136659f

typedef unsigned long long ull;

// Persistent scratch (no allocation allowed in kernel_launch).
__device__ float Xs[128 * NTOK];              // compact subsampled input
__device__ float Qg[NHEADS * NTOK * DHEAD];
__device__ float Kg[NHEADS * NTOK * DHEAD];
__device__ float Vg[NHEADS * NTOK * DHEAD];
// Partials: [4096 items][32 rows][68] : 32 acc1, 32 acc2, l1, l2, pad
__device__ float Pacc[4096 * 32 * 68];

__device__ __forceinline__ ull fma2(ull a, ull b, ull c) {
    ull d;
    asm("fma.rn.f32x2 %0, %1, %2, %3;" : "=l"(d) : "l"(a), "l"(b), "l"(c));
    return d;
}
__device__ __forceinline__ ull add2(ull a, ull b) {
    ull d;
    asm("add.rn.f32x2 %0, %1, %2;" : "=l"(d) : "l"(a), "l"(b));
    return d;
}
__device__ __forceinline__ ull pack2(float lo, float hi) {
    ull d;
    asm("mov.b64 %0, {%1, %2};" : "=l"(d) : "f"(lo), "f"(hi));
    return d;
}
__device__ __forceinline__ float2 unpack2(ull a) {
    float2 r;
    asm("mov.b64 {%0, %1}, %2;" : "=f"(r.x), "=f"(r.y) : "l"(a));
    return r;
}
__device__ __forceinline__ float ex2(float x) {
    float y;
    asm("ex2.approx.f32 %0, %1;" : "=f"(y) : "f"(x));
    return y;
}

// ---------------------------------------------------------------------------
// Gather the stride-2 subsample into a compact channel-major buffer.
// Xs[c][n], n = hh*256 + ww*16 + zz. grid 512 x 256, 4 elems/thread.
// ---------------------------------------------------------------------------
__global__ void __launch_bounds__(256) gather_kernel(const float* __restrict__ x) {
    int idx = blockIdx.x * 1024 + threadIdx.x;
#pragma unroll
    for (int i = 0; i < 4; i++, idx += 256) {
        const int c = idx >> 12;
        const int n = idx & 4095;
        const int hh = n >> 8, ww = (n >> 4) & 15, zz = n & 15;
        Xs[idx] = x[c * 32768 + hh * 2048 + ww * 64 + zz * 2];
    }
}

// ---------------------------------------------------------------------------
// QKV projection from compact Xs: block = 16 output channels x 256 tokens.
// grid (16 token-tiles, 24 o-groups), 256 threads. f32x2 inner loop.
// ---------------------------------------------------------------------------
__global__ void __launch_bounds__(256) qkv_kernel(const float* __restrict__ w) {
    __shared__ float wsT[128 * 18];   // [c][16 outputs + 2 pad], pair-aligned
    const int og  = blockIdx.y;       // 0..23 -> channels og*16 .. og*16+15
    const int nt  = blockIdx.x;       // 0..15
    const int tid = threadIdx.x;

    for (int i = tid; i < 16 * 128; i += 256) {
        const int j = i >> 7, c = i & 127;
        wsT[c * 18 + j] = w[(og * 16 + j) * 128 + c];
    }
    __syncthreads();

    const int n = nt * 256 + tid;     // token index

    ull acc[8];
#pragma unroll
    for (int j = 0; j < 8; j++) acc[j] = 0ull;

#pragma unroll 4
    for (int c = 0; c < 128; c++) {
        const float xv = Xs[c * 4096 + n];
        const ull xp = pack2(xv, xv);
        const ull* wp = (const ull*)(wsT + c * 18);
#pragma unroll
        for (int j = 0; j < 8; j++) acc[j] = fma2(xp, wp[j], acc[j]);
    }

#pragma unroll
    for (int j = 0; j < 8; j++) {
        const float2 a = unpack2(acc[j]);
        const int o0 = og * 16 + 2 * j;
        {
            const int head = o0 / 96, r = o0 % 96;
            float* dst = (r < 32) ? Qg : (r < 64 ? Kg : Vg);
            const int d = (r < 32) ? r : (r < 64 ? r - 32 : r - 64);
            dst[(head * NTOK + n) * DHEAD + d] = a.x;
        }
        {
            const int o1 = o0 + 1;
            const int head = o1 / 96, r = o1 % 96;
            float* dst = (r < 32) ? Qg : (r < 64 ? Kg : Vg);
            const int d = (r < 32) ? r : (r < 64 ? r - 32 : r - 64);
            dst[(head * NTOK + n) * DHEAD + d] = a.y;
        }
    }
}

// ---------------------------------------------------------------------------
// Differential flash attention partial pass.
// grid 4096 = 4 heads * 128 row-tiles * 8 key-eighths (512 keys each).
// Block: 128 threads = 4 warps, lane = query row; warp w takes m%4==w.
// No-max online softmax (scores O(1), exp can't overflow).
// ---------------------------------------------------------------------------
__global__ void __launch_bounds__(128, 4) attn_kernel() {
    __shared__ __align__(16) float sbuf[8448];   // tiles 8192; reduce 8448
    float* ks = sbuf;            // [128][32]
    float* vs = sbuf + 4096;     // [128][32]

    const int tid  = threadIdx.x;
    const int lane = tid & 31;
    const int warp = tid >> 5;
    const int bid  = blockIdx.x;
    const int kq   = bid & 7;                // key eighth
    const int tile = (bid >> 3) & 127;
    const int h    = bid >> 10;
    const int row  = tile * 32 + lane;

    // Load q row (32 floats), pre-scaled by scale*log2e, as 16 packed f32x2.
    const float2* qv = (const float2*)(Qg + (h * NTOK + row) * DHEAD);
    ull q1p[8], q2p[8];
#pragma unroll
    for (int j = 0; j < 8; j++) {
        const float2 a = qv[j];
        const float2 b = qv[8 + j];
        q1p[j] = pack2(a.x * QSCALE, a.y * QSCALE);
        q2p[j] = pack2(b.x * QSCALE, b.y * QSCALE);
    }

    ull acc1[16], acc2[16];
#pragma unroll
    for (int j = 0; j < 16; j++) { acc1[j] = 0ull; acc2[j] = 0ull; }
    float l1 = 0.f, l2 = 0.f;

    const float* Kh = Kg + h * NTOK * DHEAD;
    const float* Vh = Vg + h * NTOK * DHEAD;

    for (int mt = 0; mt < 4; mt++) {
        __syncthreads();
        // Stage this tile's K/V (128 keys x 32 floats) -> shared, coalesced.
        const int base4 = (kq * 512 + mt * 128) * 8;   // float4 index
#pragma unroll
        for (int i = 0; i < 8; i++) {
            const int idx = tid + i * 128;
            ((float4*)ks)[idx] = ((const float4*)Kh)[base4 + idx];
            ((float4*)vs)[idx] = ((const float4*)Vh)[base4 + idx];
        }
        __syncthreads();

#pragma unroll 2
        for (int mi = 0; mi < 32; mi++) {
            const int mm = mi * 4 + warp;
            const longlong2* kr = (const longlong2*)(ks + mm * 32);

            ull s1a = 0ull, s1b = 0ull, s2a = 0ull, s2b = 0ull;
#pragma unroll
            for (int j = 0; j < 4; j++) {
                const longlong2 ka = kr[j];       // k1 dims 4j..4j+3
                const longlong2 kb = kr[4 + j];   // k2 dims 4j..4j+3
                s1a = fma2(q1p[2 * j],     (ull)ka.x, s1a);
                s1b = fma2(q1p[2 * j + 1], (ull)ka.y, s1b);
                s2a = fma2(q2p[2 * j],     (ull)kb.x, s2a);
                s2b = fma2(q2p[2 * j + 1], (ull)kb.y, s2b);
            }
            const float2 f1 = unpack2(add2(s1a, s1b));
            const float2 f2 = unpack2(add2(s2a, s2b));
            const float e1 = ex2(f1.x + f1.y);
            const float e2 = ex2(f2.x + f2.y);
            l1 += e1; l2 += e2;
            const ull e1p = pack2(e1, e1);
            const ull e2p = pack2(e2, e2);

            const longlong2* vr = (const longlong2*)(vs + mm * 32);
#pragma unroll
            for (int j = 0; j < 8; j++) {
                const longlong2 vv = vr[j];
                acc1[2 * j]     = fma2(e1p, (ull)vv.x, acc1[2 * j]);
                acc1[2 * j + 1] = fma2(e1p, (ull)vv.y, acc1[2 * j + 1]);
                acc2[2 * j]     = fma2(e2p, (ull)vv.x, acc2[2 * j]);
                acc2[2 * j + 1] = fma2(e2p, (ull)vv.y, acc2[2 * j + 1]);
            }
        }
    }

    // --- merge the 4 warp partials through shared memory ---
    __syncthreads();
    float* red = sbuf;                            // [4][32][66]
    float* my  = red + (warp * 32 + lane) * 66;
#pragma unroll
    for (int j = 0; j < 16; j++) {
        const float2 a = unpack2(acc1[j]);
        const float2 b = unpack2(acc2[j]);
        my[2 * j]          = a.x;  my[2 * j + 1]      = a.y;
        my[32 + 2 * j]     = b.x;  my[32 + 2 * j + 1] = b.y;
    }
    my[64] = l1;  my[65] = l2;
    __syncthreads();

    const int r  = tid >> 2;          // row 0..31
    const int dg = (tid & 3) * 8;     // 8-wide d chunk
    float* P = Pacc + ((size_t)bid * 32 + r) * 68;

#pragma unroll
    for (int d = 0; d < 8; d++) {
        float a = 0.f, b = 0.f;
#pragma unroll
        for (int w = 0; w < 4; w++) {
            a += red[(w * 32 + r) * 66 + dg + d];
            b += red[(w * 32 + r) * 66 + 32 + dg + d];
        }
        P[dg + d]      = a;
        P[32 + dg + d] = b;
    }
    if ((tid & 3) == 0) {
        float l1t = 0.f, l2t = 0.f;
#pragma unroll
        for (int w = 0; w < 4; w++) {
            l1t += red[(w * 32 + r) * 66 + 64];
            l2t += red[(w * 32 + r) * 66 + 65];
        }
        P[64] = l1t;  P[65] = l2t;
    }
}

// ---------------------------------------------------------------------------
// Merge the 8 key-eighth partials and normalize. grid 512, 128 threads.
// ---------------------------------------------------------------------------
__global__ void __launch_bounds__(128) merge_kernel(float* __restrict__ out) {
    const int tid  = threadIdx.x;
    const int r    = tid >> 2;
    const int dg   = (tid & 3) * 8;
    const int h    = blockIdx.x >> 7;
    const int tile = blockIdx.x & 127;

    const float* P0 = Pacc + (((size_t)blockIdx.x * 8) * 32 + r) * 68;

    float l1 = 0.f, l2 = 0.f;
#pragma unroll
    for (int q = 0; q < 8; q++) {
        l1 += P0[q * 32 * 68 + 64];
        l2 += P0[q * 32 * 68 + 65];
    }
    const float inv1 = 1.f / l1;
    const float inv2 = LAMBDA / l2;

    float* op = out + h * (NTOK * DHEAD) + (tile * 32 + r) * DHEAD + dg;
#pragma unroll
    for (int d = 0; d < 8; d++) {
        float a = 0.f, b = 0.f;
#pragma unroll
        for (int q = 0; q < 8; q++) {
            a += P0[q * 32 * 68 + dg + d];
            b += P0[q * 32 * 68 + 32 + dg + d];
        }
        op[d] = a * inv1 - b * inv2;
    }
}

// ---------------------------------------------------------------------------
extern "C" void kernel_launch(void* const* d_in, const int* in_sizes, int n_in,
                              void* d_out, int out_size) {
    const float* x = (const float*)d_in[0];   // (1,128,32,32,32)
    const float* w = (const float*)d_in[1];   // (384,128)
    float* out = (float*)d_out;               // (1,128,16,16,16) fp32

    gather_kernel<<<512, 256>>>(x);
    dim3 qgrid(16, 24);
    qkv_kernel<<<qgrid, 256>>>(w);
    attn_kernel<<<NHEADS * 128 * 8, 128>>>();
    merge_kernel<<<NHEADS * 128, 128>>>(out);
}